// round 2
// baseline (speedup 1.0000x reference)
#include <cuda_runtime.h>

// ScorePredictor: 3x DistMult edge scoring.
// score[e] = clip( sum_d head[src[e],d] * rel[d] * tail[dst[e],d], 0, 1 )
//
// Inputs (metadata order):
//   0: x_drug    [N_DRUG * D] f32   (N_DRUG=10000, D=2048)
//   1: x_protein [N_PROT * D] f32   (N_PROT=20000)
//   2: rel_ddi   [D] f32
//   3: rel_dpi   [D] f32
//   4: ddi_src [E] i32   5: ddi_dst [E] i32
//   6: dpi_src [E] i32   7: dpi_dst [E] i32
//   8: ppi_src [E] i32   9: ppi_dst [E] i32
// Output: [3E] f32 = concat(score_ddi, score_dpi, score_ppi)

#define D_DIM 2048
#define WARPS_PER_BLOCK 8
#define THREADS_PER_BLOCK (WARPS_PER_BLOCK * 32)

__global__ __launch_bounds__(THREADS_PER_BLOCK)
void edge_score_kernel(
    const float* __restrict__ x_drug,
    const float* __restrict__ x_prot,
    const float* __restrict__ rel_ddi,
    const float* __restrict__ rel_dpi,
    const int*   __restrict__ ddi_src, const int* __restrict__ ddi_dst,
    const int*   __restrict__ dpi_src, const int* __restrict__ dpi_dst,
    const int*   __restrict__ ppi_src, const int* __restrict__ ppi_dst,
    float*       __restrict__ out,
    int E)
{
    const int warp = threadIdx.x >> 5;
    const int lane = threadIdx.x & 31;
    const long long eid = (long long)blockIdx.x * WARPS_PER_BLOCK + warp;
    const long long total = 3LL * E;
    if (eid >= total) return;

    const float* head;
    const float* tail;
    const float* rel;

    if (eid < E) {
        int e = (int)eid;
        head = x_drug + (size_t)__ldg(ddi_src + e) * D_DIM;
        tail = x_drug + (size_t)__ldg(ddi_dst + e) * D_DIM;
        rel  = rel_ddi;
    } else if (eid < 2LL * E) {
        int e = (int)(eid - E);
        head = x_drug + (size_t)__ldg(dpi_src + e) * D_DIM;
        tail = x_prot + (size_t)__ldg(dpi_dst + e) * D_DIM;
        rel  = rel_dpi;
    } else {
        int e = (int)(eid - 2LL * E);
        head = x_prot + (size_t)__ldg(ppi_src + e) * D_DIM;
        tail = x_prot + (size_t)__ldg(ppi_dst + e) * D_DIM;
        rel  = rel_dpi;   // reference (faithfully) reuses the DPI relation for PPI
    }

    float acc = 0.0f;

    // 2048 dims / warp: lane handles 16 float4 chunks, stride 32 lanes * 4.
    #pragma unroll
    for (int k = 0; k < D_DIM / (32 * 4); ++k) {
        const int idx = (k * 32 + lane) * 4;
        float4 h = *reinterpret_cast<const float4*>(head + idx);
        float4 t = *reinterpret_cast<const float4*>(tail + idx);
        float4 r = __ldg(reinterpret_cast<const float4*>(rel + idx));
        acc = fmaf(h.x * r.x, t.x, acc);
        acc = fmaf(h.y * r.y, t.y, acc);
        acc = fmaf(h.z * r.z, t.z, acc);
        acc = fmaf(h.w * r.w, t.w, acc);
    }

    // warp butterfly reduction
    #pragma unroll
    for (int off = 16; off > 0; off >>= 1)
        acc += __shfl_xor_sync(0xffffffffu, acc, off);

    if (lane == 0)
        out[eid] = fminf(fmaxf(acc, 0.0f), 1.0f);
}

extern "C" void kernel_launch(void* const* d_in, const int* in_sizes, int n_in,
                              void* d_out, int out_size)
{
    const float* x_drug  = (const float*)d_in[0];
    const float* x_prot  = (const float*)d_in[1];
    const float* rel_ddi = (const float*)d_in[2];
    const float* rel_dpi = (const float*)d_in[3];
    const int*   ddi_src = (const int*)d_in[4];
    const int*   ddi_dst = (const int*)d_in[5];
    const int*   dpi_src = (const int*)d_in[6];
    const int*   dpi_dst = (const int*)d_in[7];
    const int*   ppi_src = (const int*)d_in[8];
    const int*   ppi_dst = (const int*)d_in[9];
    float* out = (float*)d_out;

    const int E = in_sizes[4];  // edge count (100000)
    const long long total_edges = 3LL * E;
    const int blocks = (int)((total_edges + WARPS_PER_BLOCK - 1) / WARPS_PER_BLOCK);

    edge_score_kernel<<<blocks, THREADS_PER_BLOCK>>>(
        x_drug, x_prot, rel_ddi, rel_dpi,
        ddi_src, ddi_dst, dpi_src, dpi_dst, ppi_src, ppi_dst,
        out, E);
}